// round 1
// baseline (speedup 1.0000x reference)
#include <cuda_runtime.h>
#include <math.h>

#define HH 512
#define WW 512
#define NB 32
#define MS 10
#define SH 21            // 2*MS+1
#define NS 441           // SH*SH
#define NPIX (HH*WW)     // 262144
#define KWIN 492         // H - 2*MS
#define KAREA (492.0*492.0)
#define EPS 1e-8

#define TB 16                    // rows per correlation band
#define NBAND (HH/TB)            // 32
#define TROWS (TB + 20)          // 36 template rows per band
#define TCOLS (WW + 20)          // 532
#define IMG_STRIDE 516
#define CORR_THREADS 336         // 21 p-values x 16 rows
#define SMEM_CORR ((TROWS*TCOLS + TB*IMG_STRIDE) * 4)

// ---------------- scratch (device globals; no allocation) ----------------
__device__ double g_tstats[2];                 // sum(t), sum(t^2)
__device__ double g_isum[NB];                  // per-frame sum
__device__ double g_colS1[NB*SH*WW];           // column window sums
__device__ double g_colS2[NB*SH*WW];
__device__ float  g_den[NB*NS];                // denominator
__device__ float  g_ccpart[NB*NBAND*NS];       // per-band partial correlations
__device__ float  g_shift[NB*2];               // (dy, dx) per frame

// ---------------- K1: global reductions ----------------
__global__ void k_reduce(const float* __restrict__ fr, const float* __restrict__ tp) {
    __shared__ double s1[256];
    __shared__ double s2[256];
    int blk = blockIdx.x, tid = threadIdx.x;
    double a = 0.0, c = 0.0;
    if (blk < NB) {
        const float* p = fr + (size_t)blk * NPIX;
        for (int i = tid; i < NPIX; i += 256) a += (double)p[i];
    } else {
        for (int i = tid; i < NPIX; i += 256) { double v = (double)tp[i]; a += v; c += v * v; }
    }
    s1[tid] = a; s2[tid] = c;
    __syncthreads();
    for (int st = 128; st > 0; st >>= 1) {
        if (tid < st) { s1[tid] += s1[tid + st]; s2[tid] += s2[tid + st]; }
        __syncthreads();
    }
    if (tid == 0) {
        if (blk < NB) g_isum[blk] = s1[0];
        else { g_tstats[0] = s1[0]; g_tstats[1] = s2[0]; }
    }
}

// ---------------- K2: column-direction sliding window sums ----------------
__global__ void k_colwin(const float* __restrict__ fr) {
    int b = blockIdx.x;
    int x = threadIdx.x;                        // 512 threads
    const float* im = fr + (size_t)b * NPIX;
    double w1 = 0.0, w2 = 0.0;
    for (int y = 0; y < KWIN; ++y) {
        double v = (double)im[y * WW + x];
        w1 += v; w2 += v * v;
    }
    g_colS1[((size_t)b * SH + 0) * WW + x] = w1;
    g_colS2[((size_t)b * SH + 0) * WW + x] = w2;
    for (int p = 1; p <= 2 * MS; ++p) {
        double vo = (double)im[(p - 1) * WW + x];
        double vn = (double)im[(p + KWIN - 1) * WW + x];
        w1 += vn - vo;
        w2 += vn * vn - vo * vo;
        g_colS1[((size_t)b * SH + p) * WW + x] = w1;
        g_colS2[((size_t)b * SH + p) * WW + x] = w2;
    }
}

// ---------------- K3: row-direction sliding -> denominator ----------------
__global__ void k_var() {
    int b = blockIdx.x;
    int i = threadIdx.x;
    if (i >= SH) return;
    float tvar = (float)(g_tstats[1] - g_tstats[0] * g_tstats[0] / (double)NPIX + EPS);
    const double* c1 = g_colS1 + ((size_t)b * SH + i) * WW;
    const double* c2 = g_colS2 + ((size_t)b * SH + i) * WW;
    double w1 = 0.0, w2 = 0.0;
    for (int x = 0; x < KWIN; ++x) { w1 += c1[x]; w2 += c2[x]; }
    for (int j = 0; j <= 2 * MS; ++j) {
        if (j > 0) {
            w1 += c1[j + KWIN - 1] - c1[j - 1];
            w2 += c2[j + KWIN - 1] - c2[j - 1];
        }
        double m1 = w1 / KAREA;
        double m2 = w2 / KAREA;
        double var = m2 - m1 * m1 / KAREA + EPS;
        float vf = (float)var;
        if (vf < 0.f) vf = 0.f;
        g_den[(size_t)b * NS + i * SH + j] = sqrtf(tvar * vf);
    }
}

// ---------------- K4: the correlation (hot kernel) ----------------
__global__ void __launch_bounds__(CORR_THREADS, 2)
k_corr(const float* __restrict__ fr, const float* __restrict__ tp) {
    int b = blockIdx.x;
    int band = blockIdx.y;
    int y0 = band * TB;
    extern __shared__ float sm[];
    float* sm_t = sm;                       // TROWS x TCOLS
    float* sm_i = sm + TROWS * TCOLS;       // TB x IMG_STRIDE
    int tid = threadIdx.x;

    // load template tile (rows y0-10 .. y0+TB+9, cols -10..521, wrapped)
    for (int idx = tid; idx < TROWS * TCOLS; idx += CORR_THREADS) {
        int r = idx / TCOLS, c = idx - r * TCOLS;
        int gy = (y0 - MS + r) & (HH - 1);
        int gx = (c - MS) & (WW - 1);
        sm_t[idx] = tp[gy * WW + gx];
    }
    // load image band
    const float* im = fr + (size_t)b * NPIX + (size_t)y0 * WW;
    for (int idx = tid; idx < TB * WW; idx += CORR_THREADS) {
        int r = idx >> 9, c = idx & (WW - 1);
        sm_i[r * IMG_STRIDE + c] = im[idx];
    }
    __syncthreads();

    int yl = tid & 15;       // image row within band
    int p  = tid >> 4;       // shift-row index 0..20
    const float* trow = sm_t + (yl + 2 * MS - p) * TCOLS;
    const float* irow = sm_i + yl * IMG_STRIDE;

    float acc[SH];
#pragma unroll
    for (int j = 0; j < SH; ++j) acc[j] = 0.f;

    // circular register window of 21 template values, slot(col) = col mod 21
    float win[SH];
#pragma unroll
    for (int si = 0; si < 20; ++si)          // cols -10..9 at sh idx 0..19
        win[(si + 11) % SH] = trow[si];

#pragma unroll 1
    for (int xb = 0; xb < 504; xb += SH) {
#pragma unroll
        for (int u = 0; u < SH; ++u) {
            int x = xb + u;
            win[(u + 10) % SH] = trow[x + 20];   // new col x+10
            float imv = irow[x];
#pragma unroll
            for (int j = 0; j < SH; ++j)
                acc[j] = fmaf(imv, win[(u + 31 - j) % SH], acc[j]);
        }
    }
#pragma unroll
    for (int u = 0; u < 8; ++u) {                // remainder x = 504..511
        int x = 504 + u;
        win[(u + 10) % SH] = trow[x + 20];
        float imv = irow[x];
#pragma unroll
        for (int j = 0; j < SH; ++j)
            acc[j] = fmaf(imv, win[(u + 31 - j) % SH], acc[j]);
    }
    __syncthreads();

    // reduce 16 row-partials per (p, j)
    float* sred = sm;                        // reuse: 441*16 floats
#pragma unroll
    for (int j = 0; j < SH; ++j) sred[(p * SH + j) * 16 + yl] = acc[j];
    __syncthreads();
    for (int s = tid; s < NS; s += CORR_THREADS) {
        float v = 0.f;
#pragma unroll
        for (int k = 0; k < 16; ++k) v += sred[s * 16 + k];
        g_ccpart[((size_t)b * NBAND + band) * NS + s] = v;
    }
}

// ---------------- K5: ncc, argmax, subpixel shift ----------------
__global__ void k_peak() {
    int b = blockIdx.x, tid = threadIdx.x;
    __shared__ float sncc[NS];
    __shared__ float rv[512];
    __shared__ int   ri[512];
    float cfix = (float)(g_isum[b] * g_tstats[0] / (double)NPIX);
    if (tid < NS) {
        float s = 0.f;
        for (int k = 0; k < NBAND; ++k)
            s += g_ccpart[((size_t)b * NBAND + k) * NS + tid];
        float ccv = fabsf(s - cfix);
        float v = ccv / g_den[(size_t)b * NS + tid];
        if (!(v == v)) v = 0.f;                  // NaN -> 0
        sncc[tid] = v;
    }
    __syncthreads();
    rv[tid] = (tid < NS) ? sncc[tid] : -1.f;
    ri[tid] = tid;
    __syncthreads();
    for (int st = 256; st > 0; st >>= 1) {
        if (tid < st) {
            float ov = rv[tid + st]; int oi = ri[tid + st];
            if (ov > rv[tid] || (ov == rv[tid] && oi < ri[tid])) { rv[tid] = ov; ri[tid] = oi; }
        }
        __syncthreads();
    }
    if (tid == 0) {
        int am = ri[0];
        int sx = am / SH, sy = am - sx * SH;
        float shx = -(float)(sx - MS);
        float shy = -(float)(sy - MS);
        int xm = sx - 1; if (xm < 0) xm += SH;       // negative wraps (numpy)
        int xp = sx + 1; if (xp > SH - 1) xp = SH - 1; // OOB clamps (jax)
        int ym = sy - 1; if (ym < 0) ym += SH;
        int yp = sy + 1; if (yp > SH - 1) yp = SH - 1;
        float lxm = logf(sncc[xm * SH + sy]);
        float lxp = logf(sncc[xp * SH + sy]);
        float lym = logf(sncc[sx * SH + ym]);
        float lyp = logf(sncc[sx * SH + yp]);
        float lc4 = 4.f * logf(sncc[sx * SH + sy]);
        shx -= (lxm - lxp) / (2.f * lxm - lc4 + 2.f * lxp);
        shy -= (lym - lyp) / (2.f * lym - lc4 + 2.f * lyp);
        g_shift[b * 2 + 0] = shx;
        g_shift[b * 2 + 1] = shy;
    }
}

// ---------------- K6: bilinear warp + transposed store ----------------
__global__ void k_warp(const float* __restrict__ fr, float* __restrict__ out) {
    int b = blockIdx.z;
    int X0 = blockIdx.x * 32, Y0 = blockIdx.y * 32;
    float dy = g_shift[b * 2 + 0];
    float dx = g_shift[b * 2 + 1];
    __shared__ float sp[36 * 37];
    int ry = Y0 + (int)floorf(-dy) - 1;
    int rx = X0 + (int)floorf(-dx) - 1;
    const float* im = fr + (size_t)b * NPIX;
    for (int idx = threadIdx.x; idx < 36 * 36; idx += 256) {
        int r = idx / 36, c = idx - r * 36;
        int gy = ry + r, gx = rx + c;
        float v = (gy >= 0 && gy < HH && gx >= 0 && gx < WW) ? im[gy * WW + gx] : 0.f;
        sp[r * 37 + c] = v;
    }
    __syncthreads();
    int oy = threadIdx.x & 31;
    int oxb = threadIdx.x >> 5;
    for (int k = 0; k < 4; ++k) {
        int ox = oxb + 8 * k;
        int y = Y0 + oy, x = X0 + ox;
        float yq = (float)y - dy; float y0f = floorf(yq); float wy = yq - y0f;
        float xq = (float)x - dx; float x0f = floorf(xq); float wx = xq - x0f;
        int iy = (int)y0f - ry; int ix = (int)x0f - rx;
        iy = max(0, min(34, iy)); ix = max(0, min(34, ix));
        float v00 = sp[iy * 37 + ix];
        float v01 = sp[iy * 37 + ix + 1];
        float v10 = sp[(iy + 1) * 37 + ix];
        float v11 = sp[(iy + 1) * 37 + ix + 1];
        float val = v00 * (1.f - wy) * (1.f - wx) + v01 * (1.f - wy) * wx
                  + v10 * wy * (1.f - wx) + v11 * wy * wx;
        out[(size_t)b * NPIX + x * HH + y] = val;   // transposed: out[b, x*H + y]
    }
}

// ---------------- launch ----------------
extern "C" void kernel_launch(void* const* d_in, const int* in_sizes, int n_in,
                              void* d_out, int out_size) {
    const float* fr = (const float*)d_in[0];
    const float* tp = (const float*)d_in[1];
    if (n_in >= 2 && in_sizes[0] < in_sizes[1]) { const float* t = fr; fr = tp; tp = t; }
    float* out = (float*)d_out;

    cudaFuncSetAttribute(k_corr, cudaFuncAttributeMaxDynamicSharedMemorySize, SMEM_CORR);

    k_reduce<<<NB + 1, 256>>>(fr, tp);
    k_colwin<<<NB, WW>>>(fr);
    k_var<<<NB, 32>>>();
    k_corr<<<dim3(NB, NBAND), CORR_THREADS, SMEM_CORR>>>(fr, tp);
    k_peak<<<NB, 512>>>();
    k_warp<<<dim3(16, 16, NB), 256>>>(fr, out);
}

// round 2
// speedup vs baseline: 2.4096x; 2.4096x over previous
#include <cuda_runtime.h>
#include <math.h>

#define HH 512
#define WW 512
#define NB 32
#define MS 10
#define SH 21            // 2*MS+1
#define NS 441           // SH*SH
#define NPIX (HH*WW)     // 262144
#define KAREA (492.0*492.0)
#define EPS 1e-8

#define TB 16                    // rows per correlation band
#define NBAND (HH/TB)            // 32
#define TROWS (TB + 20)          // 36 template rows per band
#define TCOLS (WW + 20)          // 532
#define ISTR 516
#define CORR_THREADS 336         // 21 p-values x 16 rows
#define SMEM_CORR ((TROWS*TCOLS + 2*TB*ISTR) * 4)
#define SMEM_STATS (((512*2 + 40*2 + 512) * 8) + 40*512*4 + 64)

typedef unsigned long long u64;

// ---------------- scratch (device globals; no allocation) ----------------
__device__ double g_tstats[2];                 // sum(t), sum(t^2)
__device__ double g_isum[NB];                  // per-frame sum
__device__ double g_colF1[NB*WW];              // full column sums
__device__ double g_colF2[NB*WW];
__device__ float  g_den[NB*NS];                // denominator
__device__ float  g_ccpart[NB*NBAND*NS];       // per-band partial correlations
__device__ float  g_shift[NB*2];               // (dy, dx) per frame

// ---------------- K0: zero the atomic targets ----------------
__global__ void k_zero() {
    int i = blockIdx.x * blockDim.x + threadIdx.x;
    if (i < NB * WW) { g_colF1[i] = 0.0; g_colF2[i] = 0.0; }
    if (i < 2) g_tstats[i] = 0.0;
}

// ---------------- K1: column partial sums (frames) + template stats ----------------
__global__ void k_colpart(const float* __restrict__ fr, const float* __restrict__ tp) {
    int b = blockIdx.x;          // 0..NB (NB == template)
    int slab = blockIdx.y;       // 0..7, 64 rows each
    int x = threadIdx.x;         // 512
    const float* src = (b < NB) ? (fr + (size_t)b * NPIX) : tp;
    int y0 = slab * 64;
    float s1a = 0.f, s1b = 0.f, s2a = 0.f, s2b = 0.f;
#pragma unroll 4
    for (int y = y0; y < y0 + 64; y += 2) {
        float v0 = src[y * WW + x];
        float v1 = src[(y + 1) * WW + x];
        s1a += v0; s1b += v1;
        s2a = fmaf(v0, v0, s2a); s2b = fmaf(v1, v1, s2b);
    }
    double d1 = (double)s1a + (double)s1b;
    double d2 = (double)s2a + (double)s2b;
    if (b < NB) {
        atomicAdd(&g_colF1[b * WW + x], d1);
        atomicAdd(&g_colF2[b * WW + x], d2);
    } else {
        __shared__ double r1[512], r2[512];
        r1[x] = d1; r2[x] = d2;
        __syncthreads();
        for (int st = 256; st > 0; st >>= 1) {
            if (x < st) { r1[x] += r1[x + st]; r2[x] += r2[x + st]; }
            __syncthreads();
        }
        if (x == 0) {
            atomicAdd(&g_tstats[0], r1[0]);
            atomicAdd(&g_tstats[1], r2[0]);
        }
    }
}

// ---------------- K2: assemble all 441 window denominators per frame ----------------
__global__ void k_stats(const float* __restrict__ fr) {
    int b = blockIdx.x;
    int tid = threadIdx.x;       // 512
    extern __shared__ char dsm[];
    double* scol1 = (double*)dsm;
    double* scol2 = scol1 + 512;
    double* srow1 = scol2 + 512;
    double* srow2 = srow1 + 40;
    double* sred  = srow2 + 40;           // 512 reduction buffer
    float*  sedge = (float*)(sred + 512); // 40*512
    __shared__ double sS1, sS2;

    scol1[tid] = g_colF1[b * WW + tid];
    scol2[tid] = g_colF2[b * WW + tid];

    const float* im = fr + (size_t)b * NPIX;
    for (int idx = tid; idx < 40 * 512; idx += 512) {
        int r = idx >> 9, c = idx & 511;
        int y = (r < 20) ? r : (472 + r);
        sedge[idx] = im[y * WW + c];
    }
    __syncthreads();

    // per-edge-row sums (fp64), warp per row group
    int wid = tid >> 5, lane = tid & 31;
    for (int r = wid; r < 40; r += 16) {
        double a = 0.0, c2 = 0.0;
        for (int c = lane; c < 512; c += 32) {
            double v = (double)sedge[r * 512 + c];
            a += v; c2 += v * v;
        }
#pragma unroll
        for (int s = 16; s > 0; s >>= 1) {
            a  += __shfl_down_sync(0xffffffffu, a, s);
            c2 += __shfl_down_sync(0xffffffffu, c2, s);
        }
        if (lane == 0) { srow1[r] = a; srow2[r] = c2; }
    }
    // full-image sums via column-sum reduction
    sred[tid] = scol1[tid];
    __syncthreads();
    for (int st = 256; st > 0; st >>= 1) {
        if (tid < st) sred[tid] += sred[tid + st];
        __syncthreads();
    }
    if (tid == 0) sS1 = sred[0];
    __syncthreads();
    sred[tid] = scol2[tid];
    __syncthreads();
    for (int st = 256; st > 0; st >>= 1) {
        if (tid < st) sred[tid] += sred[tid + st];
        __syncthreads();
    }
    if (tid == 0) { sS2 = sred[0]; g_isum[b] = sS1; }
    __syncthreads();

    if (tid < NS) {
        int p = tid / SH, j = tid - p * SH;
        double rp1 = 0.0, rp2 = 0.0, rs1 = 0.0, rs2 = 0.0;
        for (int r = 0; r < p; ++r)       { rp1 += srow1[r]; rp2 += srow2[r]; }
        for (int r = p + 20; r < 40; ++r) { rs1 += srow1[r]; rs2 += srow2[r]; }
        double cp1 = 0.0, cp2 = 0.0, cs1 = 0.0, cs2 = 0.0;
        for (int c = 0; c < j; ++c)         { cp1 += scol1[c]; cp2 += scol2[c]; }
        for (int c = j + 492; c < 512; ++c) { cs1 += scol1[c]; cs2 += scol2[c]; }
        // corners (fp32 accumulate; <=400 small values each)
        float q1 = 0.f, q2 = 0.f;
        for (int r = 0; r < p; ++r) {
            for (int c = 0; c < j; ++c)         { float v = sedge[r * 512 + c]; q1 += v; q2 = fmaf(v, v, q2); }
            for (int c = j + 492; c < 512; ++c) { float v = sedge[r * 512 + c]; q1 += v; q2 = fmaf(v, v, q2); }
        }
        for (int r = p + 20; r < 40; ++r) {
            for (int c = 0; c < j; ++c)         { float v = sedge[r * 512 + c]; q1 += v; q2 = fmaf(v, v, q2); }
            for (int c = j + 492; c < 512; ++c) { float v = sedge[r * 512 + c]; q1 += v; q2 = fmaf(v, v, q2); }
        }
        double w1 = sS1 - rp1 - rs1 - cp1 - cs1 + (double)q1;
        double w2 = sS2 - rp2 - rs2 - cp2 - cs2 + (double)q2;
        double m1 = w1 / KAREA;
        double m2 = w2 / KAREA;
        double var = m2 - m1 * m1 / KAREA + EPS;
        float vf = (float)var;
        if (vf < 0.f) vf = 0.f;
        float tvar = (float)(g_tstats[1] - g_tstats[0] * g_tstats[0] / (double)NPIX + EPS);
        g_den[(size_t)b * NS + tid] = sqrtf(tvar * vf);
    }
}

// ---------------- K3: the correlation (hot kernel, packed f32x2) ----------------
__device__ __forceinline__ void ffma2(u64& d, u64 a, u64 b) {
    asm("fma.rn.f32x2 %0, %1, %2, %0;" : "+l"(d) : "l"(a), "l"(b));
}
__device__ __forceinline__ u64 ld64(const float* p) {
    return *reinterpret_cast<const u64*>(p);
}

template<int K>
__device__ __forceinline__ void corr_step(const float* irA, const float* irB,
                                          const float* trow, int x,
                                          u64* acc, u64* win, u64& imA, u64& imB) {
    u64 a = imA, bb = imB;
    imA = ld64(irA + x + 2);          // prefetch next step
    imB = ld64(irB + x + 2);
#pragma unroll
    for (int j = 0; j < SH; ++j) {
        int off = 20 - j;
        int m = (off + 1) >> 1;       // even off -> off/2 ; odd off -> (off+1)/2
        int slot = (K + m) % 12;
        if ((off & 1) == 0) ffma2(acc[j], a,  win[slot]);
        else                ffma2(acc[j], bb, win[slot]);
    }
    win[K % 12] = ld64(trow + x + 24); // refill; next consumer >= 2 steps away
}

__global__ void __launch_bounds__(CORR_THREADS, 1)
k_corr(const float* __restrict__ fr, const float* __restrict__ tp) {
    int b = blockIdx.x;
    int band = blockIdx.y;
    int y0 = band * TB;
    extern __shared__ float sm[];
    float* sm_t  = sm;                        // TROWS x TCOLS
    float* sm_iA = sm + TROWS * TCOLS;        // TB x ISTR
    float* sm_iB = sm_iA + TB * ISTR;         // TB x ISTR, shifted by 1, [511]=0
    int tid = threadIdx.x;

    for (int idx = tid; idx < TROWS * TCOLS; idx += CORR_THREADS) {
        int r = idx / TCOLS, c = idx - r * TCOLS;
        sm_t[idx] = tp[((y0 - MS + r) & (HH - 1)) * WW + ((c - MS) & (WW - 1))];
    }
    const float* im = fr + (size_t)b * NPIX + (size_t)y0 * WW;
    for (int idx = tid; idx < TB * WW; idx += CORR_THREADS) {
        int r = idx >> 9, c = idx & (WW - 1);
        float v = im[idx];
        sm_iA[r * ISTR + c] = v;
        if (c > 0)   sm_iB[r * ISTR + c - 1] = v;
        if (c == 511) sm_iB[r * ISTR + 511] = 0.f;
    }
    __syncthreads();

    int yl = tid & 15;
    int p  = tid >> 4;
    const float* trow = sm_t + (yl + 2 * MS - p) * TCOLS;
    const float* irA  = sm_iA + yl * ISTR;
    const float* irB  = sm_iB + yl * ISTR;

    u64 acc[SH];
#pragma unroll
    for (int j = 0; j < SH; j += 2) acc[j] = 0ull;
    float img0 = irA[0];
#pragma unroll
    for (int j = 1; j < SH; j += 2) {       // odd-j edge term: img[0]*T[20-j]
        float e = img0 * trow[20 - j];
        acc[j] = (u64)__float_as_uint(e);
    }
    u64 win[12];
#pragma unroll
    for (int m = 0; m < 12; ++m) win[m] = ld64(trow + 2 * m);
    u64 imA = ld64(irA);
    u64 imB = ld64(irB);

#pragma unroll 1
    for (int blk = 0; blk < 21; ++blk) {
        int xb = blk * 24;
        corr_step<0>(irA, irB, trow, xb + 0,  acc, win, imA, imB);
        corr_step<1>(irA, irB, trow, xb + 2,  acc, win, imA, imB);
        corr_step<2>(irA, irB, trow, xb + 4,  acc, win, imA, imB);
        corr_step<3>(irA, irB, trow, xb + 6,  acc, win, imA, imB);
        corr_step<4>(irA, irB, trow, xb + 8,  acc, win, imA, imB);
        corr_step<5>(irA, irB, trow, xb + 10, acc, win, imA, imB);
        corr_step<6>(irA, irB, trow, xb + 12, acc, win, imA, imB);
        corr_step<7>(irA, irB, trow, xb + 14, acc, win, imA, imB);
        corr_step<8>(irA, irB, trow, xb + 16, acc, win, imA, imB);
        corr_step<9>(irA, irB, trow, xb + 18, acc, win, imA, imB);
        corr_step<10>(irA, irB, trow, xb + 20, acc, win, imA, imB);
        corr_step<11>(irA, irB, trow, xb + 22, acc, win, imA, imB);
    }
    corr_step<0>(irA, irB, trow, 504, acc, win, imA, imB);
    corr_step<1>(irA, irB, trow, 506, acc, win, imA, imB);
    corr_step<2>(irA, irB, trow, 508, acc, win, imA, imB);
    corr_step<3>(irA, irB, trow, 510, acc, win, imA, imB);
    __syncthreads();

    // reduce 16 row-partials per (p, j)
    float* sred = sm;                        // reuse: 441*16 floats
#pragma unroll
    for (int j = 0; j < SH; ++j) {
        float lo = __uint_as_float((unsigned)(acc[j] & 0xffffffffull));
        float hi = __uint_as_float((unsigned)(acc[j] >> 32));
        sred[(p * SH + j) * 16 + yl] = lo + hi;
    }
    __syncthreads();
    for (int s = tid; s < NS; s += CORR_THREADS) {
        float v = 0.f;
#pragma unroll
        for (int k = 0; k < 16; ++k) v += sred[s * 16 + k];
        g_ccpart[((size_t)b * NBAND + band) * NS + s] = v;
    }
}

// ---------------- K4: ncc, argmax, subpixel shift ----------------
__global__ void k_peak() {
    int b = blockIdx.x, tid = threadIdx.x;
    __shared__ float sncc[NS];
    __shared__ float rv[512];
    __shared__ int   ri[512];
    float cfix = (float)(g_isum[b] * g_tstats[0] / (double)NPIX);
    if (tid < NS) {
        float s = 0.f;
        for (int k = 0; k < NBAND; ++k)
            s += g_ccpart[((size_t)b * NBAND + k) * NS + tid];
        float ccv = fabsf(s - cfix);
        float v = ccv / g_den[(size_t)b * NS + tid];
        if (!(v == v)) v = 0.f;
        sncc[tid] = v;
    }
    __syncthreads();
    rv[tid] = (tid < NS) ? sncc[tid] : -1.f;
    ri[tid] = tid;
    __syncthreads();
    for (int st = 256; st > 0; st >>= 1) {
        if (tid < st) {
            float ov = rv[tid + st]; int oi = ri[tid + st];
            if (ov > rv[tid] || (ov == rv[tid] && oi < ri[tid])) { rv[tid] = ov; ri[tid] = oi; }
        }
        __syncthreads();
    }
    if (tid == 0) {
        int am = ri[0];
        int sx = am / SH, sy = am - sx * SH;
        float shx = -(float)(sx - MS);
        float shy = -(float)(sy - MS);
        int xm = sx - 1; if (xm < 0) xm += SH;
        int xp = sx + 1; if (xp > SH - 1) xp = SH - 1;
        int ym = sy - 1; if (ym < 0) ym += SH;
        int yp = sy + 1; if (yp > SH - 1) yp = SH - 1;
        float lxm = logf(sncc[xm * SH + sy]);
        float lxp = logf(sncc[xp * SH + sy]);
        float lym = logf(sncc[sx * SH + ym]);
        float lyp = logf(sncc[sx * SH + yp]);
        float lc4 = 4.f * logf(sncc[sx * SH + sy]);
        shx -= (lxm - lxp) / (2.f * lxm - lc4 + 2.f * lxp);
        shy -= (lym - lyp) / (2.f * lym - lc4 + 2.f * lyp);
        g_shift[b * 2 + 0] = shx;
        g_shift[b * 2 + 1] = shy;
    }
}

// ---------------- K5: bilinear warp + transposed store ----------------
__global__ void k_warp(const float* __restrict__ fr, float* __restrict__ out) {
    int b = blockIdx.z;
    int X0 = blockIdx.x * 32, Y0 = blockIdx.y * 32;
    float dy = g_shift[b * 2 + 0];
    float dx = g_shift[b * 2 + 1];
    __shared__ float sp[36 * 37];
    int ry = Y0 + (int)floorf(-dy) - 1;
    int rx = X0 + (int)floorf(-dx) - 1;
    const float* im = fr + (size_t)b * NPIX;
    for (int idx = threadIdx.x; idx < 36 * 36; idx += 256) {
        int r = idx / 36, c = idx - r * 36;
        int gy = ry + r, gx = rx + c;
        float v = (gy >= 0 && gy < HH && gx >= 0 && gx < WW) ? im[gy * WW + gx] : 0.f;
        sp[r * 37 + c] = v;
    }
    __syncthreads();
    int oy = threadIdx.x & 31;
    int oxb = threadIdx.x >> 5;
    for (int k = 0; k < 4; ++k) {
        int ox = oxb + 8 * k;
        int y = Y0 + oy, x = X0 + ox;
        float yq = (float)y - dy; float y0f = floorf(yq); float wy = yq - y0f;
        float xq = (float)x - dx; float x0f = floorf(xq); float wx = xq - x0f;
        int iy = (int)y0f - ry; int ix = (int)x0f - rx;
        iy = max(0, min(34, iy)); ix = max(0, min(34, ix));
        float v00 = sp[iy * 37 + ix];
        float v01 = sp[iy * 37 + ix + 1];
        float v10 = sp[(iy + 1) * 37 + ix];
        float v11 = sp[(iy + 1) * 37 + ix + 1];
        float val = v00 * (1.f - wy) * (1.f - wx) + v01 * (1.f - wy) * wx
                  + v10 * wy * (1.f - wx) + v11 * wy * wx;
        out[(size_t)b * NPIX + x * HH + y] = val;
    }
}

// ---------------- launch ----------------
extern "C" void kernel_launch(void* const* d_in, const int* in_sizes, int n_in,
                              void* d_out, int out_size) {
    const float* fr = (const float*)d_in[0];
    const float* tp = (const float*)d_in[1];
    if (n_in >= 2 && in_sizes[0] < in_sizes[1]) { const float* t = fr; fr = tp; tp = t; }
    float* out = (float*)d_out;

    cudaFuncSetAttribute(k_corr,  cudaFuncAttributeMaxDynamicSharedMemorySize, SMEM_CORR);
    cudaFuncSetAttribute(k_stats, cudaFuncAttributeMaxDynamicSharedMemorySize, SMEM_STATS);

    k_zero<<<64, 512>>>();
    k_colpart<<<dim3(NB + 1, 8), 512>>>(fr, tp);
    k_stats<<<NB, 512, SMEM_STATS>>>(fr);
    k_corr<<<dim3(NB, NBAND), CORR_THREADS, SMEM_CORR>>>(fr, tp);
    k_peak<<<NB, 512>>>();
    k_warp<<<dim3(16, 16, NB), 256>>>(fr, out);
}

// round 4
// speedup vs baseline: 3.0588x; 1.2694x over previous
#include <cuda_runtime.h>
#include <math.h>

#define HH 512
#define WW 512
#define NB 32
#define MS 10
#define SH 21            // 2*MS+1
#define NS 441           // SH*SH
#define NPIX (HH*WW)     // 262144
#define KAREA (492.0*492.0)
#define EPS 1e-8

#define TB 16                    // rows per correlation band
#define NBAND (HH/TB)            // 32
#define TROWS (TB + 20)          // 36
#define TCOLS (WW + 20)          // 532 (x4B = 2128, 16B-aligned stride)
#define ISTR 516                 // x4B = 2064, 16B-aligned stride
#define CORR_THREADS 336         // 21 p-values x 16 rows
#define SMEM_CORR ((TROWS*TCOLS + TB*ISTR) * 4)
#define SMEM_STATS (40*512*4)

// ---------------- scratch ----------------
__device__ double g_tstats[2];
__device__ double g_isum[NB];
__device__ double g_colF1[NB*WW];
__device__ double g_colF2[NB*WW];
__device__ float  g_den[NB*NS];
__device__ float  g_ccpart[NB*NBAND*NS];
__device__ float  g_shift[NB*2];

// ---------------- K0: zero atomic targets ----------------
__global__ void k_zero() {
    int i = blockIdx.x * blockDim.x + threadIdx.x;
    if (i < NB * WW) { g_colF1[i] = 0.0; g_colF2[i] = 0.0; }
    if (i < 2) g_tstats[i] = 0.0;
}

// ---------------- K1: column partial sums + template stats ----------------
__global__ void k_colpart(const float* __restrict__ fr, const float* __restrict__ tp) {
    int b = blockIdx.x;
    int slab = blockIdx.y;
    int x = threadIdx.x;
    const float* src = (b < NB) ? (fr + (size_t)b * NPIX) : tp;
    int y0 = slab * 64;
    float s1a = 0.f, s1b = 0.f, s2a = 0.f, s2b = 0.f;
#pragma unroll 4
    for (int y = y0; y < y0 + 64; y += 2) {
        float v0 = src[y * WW + x];
        float v1 = src[(y + 1) * WW + x];
        s1a += v0; s1b += v1;
        s2a = fmaf(v0, v0, s2a); s2b = fmaf(v1, v1, s2b);
    }
    double d1 = (double)s1a + (double)s1b;
    double d2 = (double)s2a + (double)s2b;
    if (b < NB) {
        atomicAdd(&g_colF1[b * WW + x], d1);
        atomicAdd(&g_colF2[b * WW + x], d2);
    } else {
        __shared__ double r1[512], r2[512];
        r1[x] = d1; r2[x] = d2;
        __syncthreads();
        for (int st = 256; st > 0; st >>= 1) {
            if (x < st) { r1[x] += r1[x + st]; r2[x] += r2[x + st]; }
            __syncthreads();
        }
        if (x == 0) {
            atomicAdd(&g_tstats[0], r1[0]);
            atomicAdd(&g_tstats[1], r2[0]);
        }
    }
}

// ---------------- K2: all 441 window denominators per frame ----------------
__global__ void k_stats(const float* __restrict__ fr) {
    __shared__ double scol1[512], scol2[512];
    __shared__ double srow1[40], srow2[40];
    __shared__ double rowPre1[41], rowPre2[41];
    __shared__ double colPre1[21], colPre2[21];
    __shared__ double colSuf1[21], colSuf2[21];
    __shared__ double spart1[16], spart2[16];
    __shared__ double sS1s, sS2s;
    __shared__ float PP1[41*41], PP2[41*41];
    extern __shared__ float sedge[];         // 40*512

    int b = blockIdx.x, tid = threadIdx.x;   // 512 threads
    scol1[tid] = g_colF1[b * WW + tid];
    scol2[tid] = g_colF2[b * WW + tid];
    const float* im = fr + (size_t)b * NPIX;
    for (int idx = tid; idx < 40 * 512; idx += 512) {
        int r = idx >> 9, c = idx & 511;
        int y = (r < 20) ? r : (472 + r);
        sedge[idx] = im[y * WW + c];
    }
    __syncthreads();

    // phase A: edge-row sums (warps) + zero PP
    int wid = tid >> 5, lane = tid & 31;
    for (int r = wid; r < 40; r += 16) {
        double a = 0.0, c2 = 0.0;
        for (int c = lane; c < 512; c += 32) {
            double v = (double)sedge[r * 512 + c];
            a += v; c2 += v * v;
        }
#pragma unroll
        for (int s = 16; s > 0; s >>= 1) {
            a  += __shfl_down_sync(0xffffffffu, a, s);
            c2 += __shfl_down_sync(0xffffffffu, c2, s);
        }
        if (lane == 0) { srow1[r] = a; srow2[r] = c2; }
    }
    for (int idx = tid; idx < 41 * 41; idx += 512) { PP1[idx] = 0.f; PP2[idx] = 0.f; }
    __syncthreads();

    // phase B: fill PP interior (corner grid) + warp partials for full sums
    for (int idx = tid; idx < 1600; idx += 512) {
        int r = idx / 40, cc = idx - r * 40;
        int col = (cc < 20) ? cc : (472 + cc);
        float v = sedge[r * 512 + col];
        PP1[(r + 1) * 41 + cc + 1] = v;
        PP2[(r + 1) * 41 + cc + 1] = v * v;
    }
    {
        double a = scol1[tid], c2 = scol2[tid];
#pragma unroll
        for (int s = 16; s > 0; s >>= 1) {
            a  += __shfl_down_sync(0xffffffffu, a, s);
            c2 += __shfl_down_sync(0xffffffffu, c2, s);
        }
        if (lane == 0) { spart1[wid] = a; spart2[wid] = c2; }
    }
    __syncthreads();

    // phase C: horizontal prefix of PP; small fp64 prefix arrays; total sums
    if (tid < 41) {
        float a = 0.f, c2 = 0.f;
        for (int c = 0; c < 41; ++c) {
            a  += PP1[tid * 41 + c]; PP1[tid * 41 + c] = a;
            c2 += PP2[tid * 41 + c]; PP2[tid * 41 + c] = c2;
        }
    }
    if (tid == 64)  { double a = 0; rowPre1[0] = 0; for (int r = 0; r < 40; ++r) { a += srow1[r]; rowPre1[r+1] = a; } }
    if (tid == 96)  { double a = 0; rowPre2[0] = 0; for (int r = 0; r < 40; ++r) { a += srow2[r]; rowPre2[r+1] = a; } }
    if (tid == 128) { double a = 0; colPre1[0] = 0; for (int c = 0; c < 20; ++c) { a += scol1[c]; colPre1[c+1] = a; } }
    if (tid == 160) { double a = 0; colPre2[0] = 0; for (int c = 0; c < 20; ++c) { a += scol2[c]; colPre2[c+1] = a; } }
    if (tid == 192) { double a = 0; colSuf1[20] = 0; for (int j = 19; j >= 0; --j) { a += scol1[492+j]; colSuf1[j] = a; } }
    if (tid == 224) { double a = 0; colSuf2[20] = 0; for (int j = 19; j >= 0; --j) { a += scol2[492+j]; colSuf2[j] = a; } }
    if (tid == 256) { double a = 0; for (int w = 0; w < 16; ++w) a += spart1[w]; sS1s = a; g_isum[b] = a; }
    if (tid == 288) { double a = 0; for (int w = 0; w < 16; ++w) a += spart2[w]; sS2s = a; }
    __syncthreads();

    // phase D: vertical prefix of PP
    if (tid < 41) {
        float a = 0.f, c2 = 0.f;
        for (int r = 0; r < 41; ++r) {
            a  += PP1[r * 41 + tid]; PP1[r * 41 + tid] = a;
            c2 += PP2[r * 41 + tid]; PP2[r * 41 + tid] = c2;
        }
    }
    __syncthreads();

#define RECT(PP, r0, r1, c0, c1) \
    (PP[(r1)*41+(c1)] - PP[(r0)*41+(c1)] - PP[(r1)*41+(c0)] + PP[(r0)*41+(c0)])
    if (tid < NS) {
        int p = tid / SH, j = tid - p * SH;
        double rsum1 = rowPre1[p] + (rowPre1[40] - rowPre1[p + 20]);
        double rsum2 = rowPre2[p] + (rowPre2[40] - rowPre2[p + 20]);
        double csum1 = colPre1[j] + colSuf1[j];
        double csum2 = colPre2[j] + colSuf2[j];
        float q1 = RECT(PP1, 0, p, 0, j) + RECT(PP1, 0, p, 20 + j, 40)
                 + RECT(PP1, p + 20, 40, 0, j) + RECT(PP1, p + 20, 40, 20 + j, 40);
        float q2 = RECT(PP2, 0, p, 0, j) + RECT(PP2, 0, p, 20 + j, 40)
                 + RECT(PP2, p + 20, 40, 0, j) + RECT(PP2, p + 20, 40, 20 + j, 40);
        double w1 = sS1s - rsum1 - csum1 + (double)q1;
        double w2 = sS2s - rsum2 - csum2 + (double)q2;
        double m1 = w1 / KAREA;
        double m2 = w2 / KAREA;
        double var = m2 - m1 * m1 / KAREA + EPS;
        float vf = (float)var;
        if (vf < 0.f) vf = 0.f;
        float tvar = (float)(g_tstats[1] - g_tstats[0] * g_tstats[0] / (double)NPIX + EPS);
        g_den[(size_t)b * NS + tid] = sqrtf(tvar * vf);
    }
#undef RECT
}

// ---------------- K3: the correlation (hot kernel) ----------------
template<bool LAST>
__device__ __forceinline__ void corr_iter(const float* __restrict__ trow,
                                          const float* __restrict__ irow,
                                          float win[32], float acc[SH], float4& cur) {
#pragma unroll
    for (int sg = 0; sg < 8; ++sg) {
        float4 nxt = *(const float4*)(irow + 4 * sg + 4);
        float4 nw;
        const bool refill = (!LAST) || (sg <= 4);
        if (refill) nw = *(const float4*)(trow + 4 * sg + 32);
#pragma unroll
        for (int j = 0; j < SH; ++j) acc[j] = fmaf(cur.x, win[(4*sg + 0 + 20 - j) & 31], acc[j]);
#pragma unroll
        for (int j = 0; j < SH; ++j) acc[j] = fmaf(cur.y, win[(4*sg + 1 + 20 - j) & 31], acc[j]);
#pragma unroll
        for (int j = 0; j < SH; ++j) acc[j] = fmaf(cur.z, win[(4*sg + 2 + 20 - j) & 31], acc[j]);
#pragma unroll
        for (int j = 0; j < SH; ++j) acc[j] = fmaf(cur.w, win[(4*sg + 3 + 20 - j) & 31], acc[j]);
        if (refill) {
            win[(4*sg + 0) & 31] = nw.x;
            win[(4*sg + 1) & 31] = nw.y;
            win[(4*sg + 2) & 31] = nw.z;
            win[(4*sg + 3) & 31] = nw.w;
        }
        cur = nxt;
    }
}

__global__ void __launch_bounds__(CORR_THREADS, 2)
k_corr(const float* __restrict__ fr, const float* __restrict__ tp) {
    int b = blockIdx.x;
    int band = blockIdx.y;
    int y0 = band * TB;
    extern __shared__ float sm[];
    float* sm_t = sm;                       // TROWS x TCOLS
    float* sm_i = sm + TROWS * TCOLS;       // TB x ISTR
    int tid = threadIdx.x;

    for (int idx = tid; idx < TROWS * TCOLS; idx += CORR_THREADS) {
        int r = idx / TCOLS, c = idx - r * TCOLS;
        sm_t[idx] = tp[((y0 - MS + r) & (HH - 1)) * WW + ((c - MS) & (WW - 1))];
    }
    const float* im = fr + (size_t)b * NPIX + (size_t)y0 * WW;
    for (int idx = tid; idx < TB * WW; idx += CORR_THREADS) {
        int r = idx >> 9, c = idx & (WW - 1);
        sm_i[r * ISTR + c] = im[idx];
    }
    __syncthreads();

    int yl = tid & 15;
    int p  = tid >> 4;
    const float* trow = sm_t + (yl + 2 * MS - p) * TCOLS;
    const float* irow = sm_i + yl * ISTR;

    float acc[SH];
#pragma unroll
    for (int j = 0; j < SH; ++j) acc[j] = 0.f;

    float win[32];
#pragma unroll
    for (int m = 0; m < 8; ++m) {
        float4 t = *(const float4*)(trow + 4 * m);
        win[4*m + 0] = t.x; win[4*m + 1] = t.y; win[4*m + 2] = t.z; win[4*m + 3] = t.w;
    }
    float4 cur = *(const float4*)irow;

    const float* tr = trow;
    const float* ir = irow;
#pragma unroll 1
    for (int it = 0; it < 15; ++it) {
        corr_iter<false>(tr, ir, win, acc, cur);
        tr += 32; ir += 32;
    }
    corr_iter<true>(tr, ir, win, acc, cur);
    __syncthreads();

    float* sred = sm;                        // reuse: 441*16 floats
#pragma unroll
    for (int j = 0; j < SH; ++j) sred[(p * SH + j) * 16 + yl] = acc[j];
    __syncthreads();
    for (int s = tid; s < NS; s += CORR_THREADS) {
        float v = 0.f;
#pragma unroll
        for (int k = 0; k < 16; ++k) v += sred[s * 16 + k];
        g_ccpart[((size_t)b * NBAND + band) * NS + s] = v;
    }
}

// ---------------- K4: ncc, argmax, subpixel shift ----------------
__global__ void k_peak() {
    int b = blockIdx.x, tid = threadIdx.x;
    __shared__ float sncc[NS];
    __shared__ float rv[512];
    __shared__ int   ri[512];
    float cfix = (float)(g_isum[b] * g_tstats[0] / (double)NPIX);
    if (tid < NS) {
        float s = 0.f;
        for (int k = 0; k < NBAND; ++k)
            s += g_ccpart[((size_t)b * NBAND + k) * NS + tid];
        float ccv = fabsf(s - cfix);
        float v = ccv / g_den[(size_t)b * NS + tid];
        if (!(v == v)) v = 0.f;
        sncc[tid] = v;
    }
    __syncthreads();
    rv[tid] = (tid < NS) ? sncc[tid] : -1.f;
    ri[tid] = tid;
    __syncthreads();
    for (int st = 256; st > 0; st >>= 1) {
        if (tid < st) {
            float ov = rv[tid + st]; int oi = ri[tid + st];
            if (ov > rv[tid] || (ov == rv[tid] && oi < ri[tid])) { rv[tid] = ov; ri[tid] = oi; }
        }
        __syncthreads();
    }
    if (tid == 0) {
        int am = ri[0];
        int sx = am / SH, sy = am - sx * SH;
        float shx = -(float)(sx - MS);
        float shy = -(float)(sy - MS);
        int xm = sx - 1; if (xm < 0) xm += SH;
        int xp = sx + 1; if (xp > SH - 1) xp = SH - 1;
        int ym = sy - 1; if (ym < 0) ym += SH;
        int yp = sy + 1; if (yp > SH - 1) yp = SH - 1;
        float lxm = logf(sncc[xm * SH + sy]);
        float lxp = logf(sncc[xp * SH + sy]);
        float lym = logf(sncc[sx * SH + ym]);
        float lyp = logf(sncc[sx * SH + yp]);
        float lc4 = 4.f * logf(sncc[sx * SH + sy]);
        shx -= (lxm - lxp) / (2.f * lxm - lc4 + 2.f * lxp);
        shy -= (lym - lyp) / (2.f * lym - lc4 + 2.f * lyp);
        g_shift[b * 2 + 0] = shx;
        g_shift[b * 2 + 1] = shy;
    }
}

// ---------------- K5: bilinear warp + transposed store ----------------
__global__ void k_warp(const float* __restrict__ fr, float* __restrict__ out) {
    int b = blockIdx.z;
    int X0 = blockIdx.x * 32, Y0 = blockIdx.y * 32;
    float dy = g_shift[b * 2 + 0];
    float dx = g_shift[b * 2 + 1];
    __shared__ float sp[36 * 37];
    int ry = Y0 + (int)floorf(-dy) - 1;
    int rx = X0 + (int)floorf(-dx) - 1;
    const float* im = fr + (size_t)b * NPIX;
    for (int idx = threadIdx.x; idx < 36 * 36; idx += 256) {
        int r = idx / 36, c = idx - r * 36;
        int gy = ry + r, gx = rx + c;
        float v = (gy >= 0 && gy < HH && gx >= 0 && gx < WW) ? im[gy * WW + gx] : 0.f;
        sp[r * 37 + c] = v;
    }
    __syncthreads();
    int oy = threadIdx.x & 31;
    int oxb = threadIdx.x >> 5;
    for (int k = 0; k < 4; ++k) {
        int ox = oxb + 8 * k;
        int y = Y0 + oy, x = X0 + ox;
        float yq = (float)y - dy; float y0f = floorf(yq); float wy = yq - y0f;
        float xq = (float)x - dx; float x0f = floorf(xq); float wx = xq - x0f;
        int iy = (int)y0f - ry; int ix = (int)x0f - rx;
        iy = max(0, min(34, iy)); ix = max(0, min(34, ix));
        float v00 = sp[iy * 37 + ix];
        float v01 = sp[iy * 37 + ix + 1];
        float v10 = sp[(iy + 1) * 37 + ix];
        float v11 = sp[(iy + 1) * 37 + ix + 1];
        float val = v00 * (1.f - wy) * (1.f - wx) + v01 * (1.f - wy) * wx
                  + v10 * wy * (1.f - wx) + v11 * wy * wx;
        out[(size_t)b * NPIX + x * HH + y] = val;
    }
}

// ---------------- launch ----------------
extern "C" void kernel_launch(void* const* d_in, const int* in_sizes, int n_in,
                              void* d_out, int out_size) {
    const float* fr = (const float*)d_in[0];
    const float* tp = (const float*)d_in[1];
    if (n_in >= 2 && in_sizes[0] < in_sizes[1]) { const float* t = fr; fr = tp; tp = t; }
    float* out = (float*)d_out;

    cudaFuncSetAttribute(k_corr,  cudaFuncAttributeMaxDynamicSharedMemorySize, SMEM_CORR);
    cudaFuncSetAttribute(k_stats, cudaFuncAttributeMaxDynamicSharedMemorySize, SMEM_STATS);

    k_zero<<<64, 512>>>();
    k_colpart<<<dim3(NB + 1, 8), 512>>>(fr, tp);
    k_stats<<<NB, 512, SMEM_STATS>>>(fr);
    k_corr<<<dim3(NB, NBAND), CORR_THREADS, SMEM_CORR>>>(fr, tp);
    k_peak<<<NB, 512>>>();
    k_warp<<<dim3(16, 16, NB), 256>>>(fr, out);
}